// round 8
// baseline (speedup 1.0000x reference)
#include <cuda_runtime.h>
#include <cstdint>

// Problem constants
#define B_  256
#define T_  512
#define I_  64
#define H_  512
#define O_  16

// Tiling: cluster of 8 CTAs covers H=512 (64 j each) for a 16-batch group.
#define HC        64
#define NB        16
#define CLUSTER_X 8
#define GRID_Y    16
#define NTHR      512
#define NSLICE    8
#define KTOT      576        // unified k: 0..63 = x/W_ih, 64..575 = h/W_hh
#define KSL       72         // k per slice

// Shared memory layout (bytes)
//   smW   : float [576][64]   147456  rows 0..63 W_ih^T, 64..575 W_hh^T  [k][j_local]
//   hdup  : float2[512][16]    65536  h_t duplicated pairs [k][b_local]; ALIASED by part
//   part  : float4[8][64][4]   32768  split-K partials (aliases hdup, sync-separated)
//   xs    : float [64][16]      4096  x_t (non-dup) [i][b_local]
//   biasv : float [64]           256
#define SM_W_OFF    0
#define SM_H_OFF    147456
#define SM_X_OFF    212992
#define SM_BV_OFF   217088
#define SMEM_BYTES  217344

// Hidden state ping-pong, stored TRANSPOSED: hT[k][b]
__device__ float g_hTA[H_ * B_];
__device__ float g_hTB[H_ * B_];
__device__ float g_hT0[H_ * B_];

// Packed fp32x2 FMA: d = a*b + d  (SASS FFMA2)
__device__ __forceinline__ void ffma2(float2& d, float2 a, float2 b) {
    unsigned long long& dd = reinterpret_cast<unsigned long long&>(d);
    unsigned long long  aa = *reinterpret_cast<unsigned long long*>(&a);
    unsigned long long  bb = *reinterpret_cast<unsigned long long*>(&b);
    asm("fma.rn.f32x2 %0, %1, %2, %0;" : "+l"(dd) : "l"(aa), "l"(bb));
}

// h0[1][B][H] -> g_hT0[k][b]
__global__ void __launch_bounds__(256) init_hT0_kernel(const float* __restrict__ h0) {
    int idx = blockIdx.x * 256 + threadIdx.x;      // 0..32767
    int b  = idx >> 7;
    int k0 = (idx & 127) << 2;
    float4 v = *reinterpret_cast<const float4*>(h0 + (size_t)b * H_ + k0);
    g_hT0[(k0 + 0) * B_ + b] = v.x;
    g_hT0[(k0 + 1) * B_ + b] = v.y;
    g_hT0[(k0 + 2) * B_ + b] = v.z;
    g_hT0[(k0 + 3) * B_ + b] = v.w;
}

__global__ void __launch_bounds__(NTHR, 1) __cluster_dims__(CLUSTER_X, 1, 1)
rnn_kernel(const float* __restrict__ x,
           const float* __restrict__ W_ih,
           const float* __restrict__ W_hh,
           const float* __restrict__ b_ih,
           const float* __restrict__ b_hh,
           const float* __restrict__ W_fc,
           const float* __restrict__ b_fc,
           float* __restrict__ out, int out_size) {
    extern __shared__ char smem[];
    float*  smW   = reinterpret_cast<float*>(smem + SM_W_OFF);
    float2* hdup  = reinterpret_cast<float2*>(smem + SM_H_OFF);
    float*  xs    = reinterpret_cast<float*>(smem + SM_X_OFF);
    float*  biasv = reinterpret_cast<float*>(smem + SM_BV_OFF);
    float4* part4 = reinterpret_cast<float4*>(smem + SM_H_OFF);   // aliases hdup
    const float4* W4  = reinterpret_cast<const float4*>(smW);
    const float4* H4  = reinterpret_cast<const float4*>(hdup);
    const float4* Xs4 = reinterpret_cast<const float4*>(xs);
    float4* H4s = reinterpret_cast<float4*>(hdup);

    const int tid   = threadIdx.x;
    const int slice = tid >> 6;          // 8 slices x 64 threads (2 warps)
    const int sth   = tid & 63;
    const int jg    = sth & 15;          // 4 j each
    const int bq    = sth >> 4;          // 4 b each
    const int hc0 = blockIdx.x * HC;
    const int bb0 = blockIdx.y * NB;

    // ---- One-time: stage W (unified, transposed) ----
    for (int idx = tid; idx < HC * 512; idx += NTHR) {
        int j = idx >> 9, k = idx & 511;
        smW[(k + 64) * 64 + j] = W_hh[(hc0 + j) * 512 + k];
    }
    for (int idx = tid; idx < HC * 64; idx += NTHR) {
        int j = idx >> 6, i = idx & 63;
        smW[i * 64 + j] = W_ih[(hc0 + j) * 64 + i];
    }
    if (tid < HC) biasv[tid] = b_ih[hc0 + tid] + b_hh[hc0 + tid];

    // x staging: xs[i][b] (non-dup). 256 threads.
    #define STAGE_X(tt)                                                          \
    if (tid < 256) {                                                             \
        int b_  = tid & 15;                                                      \
        int iq_ = tid >> 4;                                                      \
        float4 v_ = __ldg(reinterpret_cast<const float4*>(                       \
                        x + ((size_t)(bb0 + b_) * T_ + (tt)) * I_ + iq_ * 4));   \
        xs[(iq_ * 4 + 0) * 16 + b_] = v_.x;                                      \
        xs[(iq_ * 4 + 1) * 16 + b_] = v_.y;                                      \
        xs[(iq_ * 4 + 2) * 16 + b_] = v_.z;                                      \
        xs[(iq_ * 4 + 3) * 16 + b_] = v_.w;                                      \
    }

    STAGE_X(0);

    const int k0 = slice * KSL;
    const int k1 = k0 + KSL;
    const int kx1 = (k0 < 64) ? 64 : k0;          // x-rows end (slice 0 only)
    const int kh0 = (k0 < 64) ? 0 : (k0 - 64);    // h-row range
    const int kh1 = k1 - 64;

    for (int t = 0; t < T_; t++) {
        const float* src = (t == 0) ? g_hT0 : ((t & 1) ? g_hTB : g_hTA);
        float*       dst = (t & 1) ? g_hTA : g_hTB;

        // ---- Stage h: front-batch 4 L2 loads (MLP=4), then dup-write ----
        float4 hv4[4];
        #pragma unroll
        for (int r = 0; r < 4; r++) {
            int u = r * NTHR + tid;
            int k = u >> 2;
            int c = (u & 3) << 2;
            hv4[r] = __ldcg(reinterpret_cast<const float4*>(src + k * B_ + bb0 + c));
        }
        #pragma unroll
        for (int r = 0; r < 4; r++) {
            int u = r * NTHR + tid;
            int k = u >> 2;
            int c = (u & 3) << 2;
            H4s[k * 8 + (c >> 1) + 0] = make_float4(hv4[r].x, hv4[r].x, hv4[r].y, hv4[r].y);
            H4s[k * 8 + (c >> 1) + 1] = make_float4(hv4[r].z, hv4[r].z, hv4[r].w, hv4[r].w);
        }
        __syncthreads();

        // ---- Compute slice partials: 4j x 4b tile ----
        float2 a0[4], a1[4];   // a0: (j0,j1) x 4b ; a1: (j2,j3) x 4b
        #pragma unroll
        for (int bb = 0; bb < 4; bb++) { a0[bb] = make_float2(0.f, 0.f); a1[bb] = make_float2(0.f, 0.f); }

        // x portion (slice 0 only)
        for (int k = k0; k < kx1; k++) {
            float4 w  = W4[k * 16 + jg];
            float4 xv = Xs4[k * 4 + bq];
            ffma2(a0[0], make_float2(w.x, w.y), make_float2(xv.x, xv.x));
            ffma2(a1[0], make_float2(w.z, w.w), make_float2(xv.x, xv.x));
            ffma2(a0[1], make_float2(w.x, w.y), make_float2(xv.y, xv.y));
            ffma2(a1[1], make_float2(w.z, w.w), make_float2(xv.y, xv.y));
            ffma2(a0[2], make_float2(w.x, w.y), make_float2(xv.z, xv.z));
            ffma2(a1[2], make_float2(w.z, w.w), make_float2(xv.z, xv.z));
            ffma2(a0[3], make_float2(w.x, w.y), make_float2(xv.w, xv.w));
            ffma2(a1[3], make_float2(w.z, w.w), make_float2(xv.w, xv.w));
        }
        // h portion
        #pragma unroll 4
        for (int k = kh0; k < kh1; k++) {
            float4 w   = W4[(k + 64) * 16 + jg];
            float4 h01 = H4[k * 8 + bq * 2 + 0];   // (hb0,hb0,hb1,hb1)
            float4 h23 = H4[k * 8 + bq * 2 + 1];   // (hb2,hb2,hb3,hb3)
            ffma2(a0[0], make_float2(w.x, w.y), make_float2(h01.x, h01.y));
            ffma2(a1[0], make_float2(w.z, w.w), make_float2(h01.x, h01.y));
            ffma2(a0[1], make_float2(w.x, w.y), make_float2(h01.z, h01.w));
            ffma2(a1[1], make_float2(w.z, w.w), make_float2(h01.z, h01.w));
            ffma2(a0[2], make_float2(w.x, w.y), make_float2(h23.x, h23.y));
            ffma2(a1[2], make_float2(w.z, w.w), make_float2(h23.x, h23.y));
            ffma2(a0[3], make_float2(w.x, w.y), make_float2(h23.z, h23.w));
            ffma2(a1[3], make_float2(w.z, w.w), make_float2(h23.z, h23.w));
        }
        __syncthreads();   // all hdup/xs reads done -> part may alias hdup

        // ---- Write partials: part[slice][sth][jx] = (out_j, b0..b3) ----
        {
            float4* p = part4 + (size_t)(slice * 64 + sth) * 4;
            p[0] = make_float4(a0[0].x, a0[1].x, a0[2].x, a0[3].x);  // j = jg*4+0
            p[1] = make_float4(a0[0].y, a0[1].y, a0[2].y, a0[3].y);  // j+1
            p[2] = make_float4(a1[0].x, a1[1].x, a1[2].x, a1[3].x);  // j+2
            p[3] = make_float4(a1[0].y, a1[1].y, a1[2].y, a1[3].y);  // j+3
        }
        __syncthreads();

        // ---- Reduce 8 slices + bias + relu + store (256 threads) ----
        if (tid < 256) {
            int th = tid >> 2, jx = tid & 3;
            float4 s = part4[(size_t)(0 * 64 + th) * 4 + jx];
            #pragma unroll
            for (int sl = 1; sl < NSLICE; sl++) {
                float4 p = part4[(size_t)(sl * 64 + th) * 4 + jx];
                s.x += p.x; s.y += p.y; s.z += p.z; s.w += p.w;
            }
            int j  = (th & 15) * 4 + jx;
            int gb = bb0 + (th >> 4) * 4;
            float bv = biasv[j];
            float4 r4;
            r4.x = fmaxf(s.x + bv, 0.f);
            r4.y = fmaxf(s.y + bv, 0.f);
            r4.z = fmaxf(s.z + bv, 0.f);
            r4.w = fmaxf(s.w + bv, 0.f);
            *reinterpret_cast<float4*>(dst + (size_t)(hc0 + j) * B_ + gb) = r4;
        }

        // Release stores to cluster; overlap x(t+1) staging with the wait.
        asm volatile("barrier.cluster.arrive.aligned;" ::: "memory");
        if (t + 1 < T_) STAGE_X(t + 1);
        asm volatile("barrier.cluster.wait.aligned;" ::: "memory");
    }

    // ================= Fused FC epilogue =================
    // Final h in g_hTA (t=511 odd). Each CTA: 2 batches.
    int out_off = -1, h_off = -1;
    if (out_size >= B_ * O_ + B_ * H_)      { out_off = 0; h_off = B_ * O_; }
    else if (out_size == B_ * O_)           { out_off = 0; }
    else if (out_size == B_ * H_)           { h_off = 0; }
    else                                    { out_off = 0; }

    const int myb0 = bb0 + (blockIdx.x << 1);
    float* hs = reinterpret_cast<float*>(smem + SM_H_OFF);   // reuse: [2][512]

    for (int u = tid; u < 2 * H_; u += NTHR) {
        int b = u >> 9, k = u & 511;
        float v = __ldcg(g_hTA + k * B_ + myb0 + b);
        hs[b * H_ + k] = v;
        if (h_off >= 0) out[h_off + (size_t)(myb0 + b) * H_ + k] = v;
    }
    __syncthreads();

    if (out_off >= 0) {
        int w  = tid >> 5, ln = tid & 31;
        if (w < 8) {
            int b  = w >> 2;                 // 0..1
            int ob = (w & 3) << 2;           // 0,4,8,12
            #pragma unroll
            for (int oo = 0; oo < 4; oo++) {
                int o = ob + oo;
                float s = 0.f;
                #pragma unroll
                for (int k = ln; k < H_; k += 32)
                    s += hs[b * H_ + k] * W_fc[(size_t)o * H_ + k];
                #pragma unroll
                for (int d = 16; d > 0; d >>= 1)
                    s += __shfl_down_sync(0xFFFFFFFFu, s, d);
                if (ln == 0)
                    out[out_off + (size_t)(myb0 + b) * O_ + o] = s + b_fc[o];
            }
        }
    }
}

extern "C" void kernel_launch(void* const* d_in, const int* in_sizes, int n_in,
                              void* d_out, int out_size) {
    const float* x    = (const float*)d_in[0];
    const float* h0   = (const float*)d_in[1];
    const float* W_ih = (const float*)d_in[2];
    const float* W_hh = (const float*)d_in[3];
    const float* b_ih = (const float*)d_in[4];
    const float* b_hh = (const float*)d_in[5];
    const float* W_fc = (const float*)d_in[6];
    const float* b_fc = (const float*)d_in[7];
    float* out = (float*)d_out;

    cudaFuncSetAttribute(rnn_kernel,
                         cudaFuncAttributeMaxDynamicSharedMemorySize, SMEM_BYTES);

    init_hT0_kernel<<<128, 256>>>(h0);
    dim3 grid(CLUSTER_X, GRID_Y);
    rnn_kernel<<<grid, NTHR, SMEM_BYTES>>>(x, W_ih, W_hh, b_ih, b_hh,
                                           W_fc, b_fc, out, out_size);
}

// round 10
// speedup vs baseline: 1.9787x; 1.9787x over previous
#include <cuda_runtime.h>
#include <cuda_fp16.h>
#include <cstdint>

#define B_ 256
#define T_ 512
#define I_ 64
#define H_ 512
#define O_ 16
#define NTHR 512
#define CLX 8
#define GRID_Y 16

#define PITCH 520                 // f16 elems per staged-h row (padded vs 512)
#define SM_HHI 0                  // h hi stage: 16 rows x 1040 B
#define SM_HLO 16768              // h lo stage
#define SM_R   33536              // split-K partials: 8 x 32 x float4 = 4 KB
#define SMEM_BYTES 37696

#define INV2048 4.8828125e-4f

// Exchange buffers (f16 hi / scaled-lo), ping-pong; xp; final h
__device__ __half g_hHi[2][B_][H_];
__device__ __half g_hLo[2][B_][H_];
__device__ float  g_xp[(size_t)T_ * B_ * H_];
__device__ float  g_hfin[B_ * H_];

// ---------------- helpers ----------------
__device__ __forceinline__ void ffma2(float2& d, float2 a, float2 b) {
    unsigned long long& dd = reinterpret_cast<unsigned long long&>(d);
    unsigned long long  aa = *reinterpret_cast<unsigned long long*>(&a);
    unsigned long long  bb = *reinterpret_cast<unsigned long long*>(&b);
    asm("fma.rn.f32x2 %0, %1, %2, %0;" : "+l"(dd) : "l"(aa), "l"(bb));
}
__device__ __forceinline__ uint32_t smem_u32(const void* p) {
    uint32_t a;
    asm("{ .reg .u64 t; cvta.to.shared.u64 t, %1; cvt.u32.u64 %0, t; }" : "=r"(a) : "l"(p));
    return a;
}
__device__ __forceinline__ void mma16816(float* d, const uint32_t* a, const uint32_t* b) {
    asm volatile(
        "mma.sync.aligned.m16n8k16.row.col.f32.f16.f16.f32 "
        "{%0,%1,%2,%3}, {%4,%5,%6,%7}, {%8,%9}, {%0,%1,%2,%3};"
        : "+f"(d[0]), "+f"(d[1]), "+f"(d[2]), "+f"(d[3])
        : "r"(a[0]), "r"(a[1]), "r"(a[2]), "r"(a[3]), "r"(b[0]), "r"(b[1]));
}
__device__ __forceinline__ void ldsm4(uint32_t* a, uint32_t addr) {
    asm volatile("ldmatrix.sync.aligned.m8n8.x4.shared.b16 {%0,%1,%2,%3}, [%4];"
                 : "=r"(a[0]), "=r"(a[1]), "=r"(a[2]), "=r"(a[3]) : "r"(addr));
}
__device__ __forceinline__ uint32_t pack_hilo(float v0, float v1, float scale, uint32_t& lo) {
    __half h0 = __float2half_rn(v0), h1 = __float2half_rn(v1);
    __half l0 = __float2half_rn((v0 - __half2float(h0)) * scale);
    __half l1 = __float2half_rn((v1 - __half2float(h1)) * scale);
    __half2 lp = __halves2half2(l0, l1);
    lo = *reinterpret_cast<uint32_t*>(&lp);
    __half2 hp = __halves2half2(h0, h1);
    return *reinterpret_cast<uint32_t*>(&hp);
}

// ---------------- pre-kernels ----------------
// xp[t][b][j] = sum_i x[b][t][i]*W_ih[j][i] + b_ih[j] + b_hh[j]   (exact fp32)
__global__ void __launch_bounds__(256) xp_kernel(const float* __restrict__ x,
                                                 const float* __restrict__ W_ih,
                                                 const float* __restrict__ b_ih,
                                                 const float* __restrict__ b_hh) {
    __shared__ float w[64 * 64];     // [i][j]
    __shared__ float xs[32 * 65];    // [b][i] padded
    const int t = blockIdx.x;
    const int bc = blockIdx.y >> 3, jc = blockIdx.y & 7;
    const int tid = threadIdx.x;
    for (int u = tid; u < 4096; u += 256) {
        int j = u >> 6, i = u & 63;
        w[i * 64 + j] = W_ih[(jc * 64 + j) * 64 + i];
    }
    #pragma unroll
    for (int r = 0; r < 2; r++) {
        int v = r * 256 + tid;
        int b = v >> 4, i4 = v & 15;
        float4 q = __ldg((const float4*)(x + ((size_t)(bc * 32 + b) * T_ + t) * 64) + i4);
        xs[b * 65 + i4 * 4 + 0] = q.x; xs[b * 65 + i4 * 4 + 1] = q.y;
        xs[b * 65 + i4 * 4 + 2] = q.z; xs[b * 65 + i4 * 4 + 3] = q.w;
    }
    __syncthreads();
    const int b = tid & 31, jg = tid >> 5, j0 = jg * 8;
    float2 acc[4];
    #pragma unroll
    for (int p = 0; p < 4; p++) {
        int j = jc * 64 + j0 + 2 * p;
        acc[p] = make_float2(b_ih[j] + b_hh[j], b_ih[j + 1] + b_hh[j + 1]);
    }
    #pragma unroll 8
    for (int i = 0; i < 64; i++) {
        float xi = xs[b * 65 + i];
        float4 wa = *(const float4*)(w + i * 64 + j0);
        float4 wb = *(const float4*)(w + i * 64 + j0 + 4);
        float2 xd = make_float2(xi, xi);
        ffma2(acc[0], make_float2(wa.x, wa.y), xd);
        ffma2(acc[1], make_float2(wa.z, wa.w), xd);
        ffma2(acc[2], make_float2(wb.x, wb.y), xd);
        ffma2(acc[3], make_float2(wb.z, wb.w), xd);
    }
    float* dst = g_xp + ((size_t)t * 256 + bc * 32 + b) * 512 + jc * 64 + j0;
    *(float4*)dst       = make_float4(acc[0].x, acc[0].y, acc[1].x, acc[1].y);
    *(float4*)(dst + 4) = make_float4(acc[2].x, acc[2].y, acc[3].x, acc[3].y);
}

// h0 -> f16 hi / scaled-lo exchange buffer (ping 0)
__global__ void __launch_bounds__(256) h0_kernel(const float* __restrict__ h0) {
    int e = blockIdx.x * 256 + threadIdx.x;     // grid 512 -> 131072
    int b = e >> 9, k = e & 511;
    float v = h0[(size_t)b * 512 + k];
    __half hi = __float2half_rn(v);
    __half lo = __float2half_rn((v - __half2float(hi)) * 2048.0f);
    g_hHi[0][b][k] = hi;
    g_hLo[0][b][k] = lo;
}

// ---------------- main persistent RNN kernel ----------------
__global__ void __launch_bounds__(NTHR, 1) __cluster_dims__(CLX, 1, 1)
rnn_kernel(const float* __restrict__ Whh, const float* __restrict__ Wfc,
           const float* __restrict__ bfc, float* __restrict__ out, int out_size) {
    extern __shared__ char smem[];
    const uint32_t hh_b = smem_u32(smem + SM_HHI);
    const uint32_t hl_b = smem_u32(smem + SM_HLO);
    float4* rbuf = (float4*)(smem + SM_R);

    const int tid = threadIdx.x, lane = tid & 31, warp = tid >> 5;
    const int wn = warp & 7;          // n-tile: j0 = wn*8
    const int kh = warp >> 3;         // k-half: 0 -> k[0,256), 1 -> k[256,512)
    const int jcb = blockIdx.x, bg = blockIdx.y;
    const int hc0 = jcb * 64, bb0 = bg * 16;

    // ---- One-time: W fragments (B operand) into registers, f16 hi/lo ----
    uint32_t bhi[16][2], blo[16][2];
    {
        const int jB = hc0 + wn * 8 + (lane >> 2);
        #pragma unroll
        for (int ks = 0; ks < 16; ks++) {
            int kb = kh * 256 + ks * 16 + (lane & 3) * 2;
            #pragma unroll
            for (int r = 0; r < 2; r++) {
                float2 w = *(const float2*)&Whh[(size_t)jB * 512 + kb + r * 8];
                bhi[ks][r] = pack_hilo(w.x, w.y, 2048.0f, blo[ks][r]);
            }
        }
    }

    int out_off = -1, h_off = -1;
    if (out_size >= B_ * O_ + B_ * H_)      { out_off = 0; h_off = B_ * O_; }
    else if (out_size == B_ * O_)           { out_off = 0; }
    else if (out_size == B_ * H_)           { h_off = 0; }
    else                                    { out_off = 0; }

    const int srow = tid >> 5;        // staged h row (batch) this warp fills
    const int sseg = tid & 31;        // 16-f16 segment within row
    const uint32_t la_hi = hh_b + (lane & 15) * (PITCH * 2) + ((lane >> 4) * 8 + kh * 256) * 2;
    const uint32_t la_lo = hl_b + (lane & 15) * (PITCH * 2) + ((lane >> 4) * 8 + kh * 256) * 2;
    const int bl0 = lane >> 2, bl1 = bl0 + 8;       // C-frag rows (batches)
    const int jg = hc0 + wn * 8 + (lane & 3) * 2;   // C-frag cols (j pair)

    for (int t = 0; t < T_; t++) {
        const int ping = t & 1, pong = ping ^ 1;

        // xp prefetch (independent of h -> overlaps everything)
        float2 xv0 = make_float2(0.f, 0.f), xv1 = make_float2(0.f, 0.f);
        if (kh == 0) {
            xv0 = *(const float2*)&g_xp[((size_t)t * B_ + bb0 + bl0) * H_ + jg];
            xv1 = *(const float2*)&g_xp[((size_t)t * B_ + bb0 + bl1) * H_ + jg];
        }

        // ---- stage h (front-batched L2 loads, then STS) ----
        uint4 q0, q1, q2, q3;
        {
            const uint4* sh = (const uint4*)&g_hHi[ping][bb0 + srow][sseg * 16];
            const uint4* sl = (const uint4*)&g_hLo[ping][bb0 + srow][sseg * 16];
            q0 = __ldcg(sh); q1 = __ldcg(sh + 1);
            q2 = __ldcg(sl); q3 = __ldcg(sl + 1);
        }
        {
            char* dh = smem + SM_HHI + srow * (PITCH * 2) + sseg * 32;
            char* dl = smem + SM_HLO + srow * (PITCH * 2) + sseg * 32;
            *(uint4*)dh = q0; *(uint4*)(dh + 16) = q1;
            *(uint4*)dl = q2; *(uint4*)(dl + 16) = q3;
        }
        __syncthreads();

        // ---- 3-pass split mma over this warp's k-half ----
        float Dm[4] = {0, 0, 0, 0}, Da[4] = {0, 0, 0, 0}, Db[4] = {0, 0, 0, 0};
        #pragma unroll
        for (int ks = 0; ks < 16; ks++) {
            uint32_t ah[4], al[4];
            ldsm4(ah, la_hi + ks * 32);
            ldsm4(al, la_lo + ks * 32);
            mma16816(Dm, ah, bhi[ks]);
            mma16816(Da, ah, blo[ks]);
            mma16816(Db, al, bhi[ks]);
        }
        float pr[4];
        #pragma unroll
        for (int p = 0; p < 4; p++) pr[p] = Dm[p] + (Da[p] + Db[p]) * INV2048;

        if (kh == 1) rbuf[wn * 32 + lane] = make_float4(pr[0], pr[1], pr[2], pr[3]);
        __syncthreads();

        // ---- epilogue: merge halves, +xp, relu, split, exchange store ----
        if (kh == 0) {
            float4 o = rbuf[wn * 32 + lane];
            float v00 = fmaxf(pr[0] + o.x + xv0.x, 0.f);
            float v01 = fmaxf(pr[1] + o.y + xv0.y, 0.f);
            float v10 = fmaxf(pr[2] + o.z + xv1.x, 0.f);
            float v11 = fmaxf(pr[3] + o.w + xv1.y, 0.f);
            uint32_t lo0, lo1;
            uint32_t hi0 = pack_hilo(v00, v01, 2048.0f, lo0);
            uint32_t hi1 = pack_hilo(v10, v11, 2048.0f, lo1);
            *(uint32_t*)&g_hHi[pong][bb0 + bl0][jg] = hi0;
            *(uint32_t*)&g_hLo[pong][bb0 + bl0][jg] = lo0;
            *(uint32_t*)&g_hHi[pong][bb0 + bl1][jg] = hi1;
            *(uint32_t*)&g_hLo[pong][bb0 + bl1][jg] = lo1;
            if (t == T_ - 1) {
                *(float2*)&g_hfin[(size_t)(bb0 + bl0) * H_ + jg] = make_float2(v00, v01);
                *(float2*)&g_hfin[(size_t)(bb0 + bl1) * H_ + jg] = make_float2(v10, v11);
                if (h_off >= 0) {
                    *(float2*)&out[h_off + (size_t)(bb0 + bl0) * H_ + jg] = make_float2(v00, v01);
                    *(float2*)&out[h_off + (size_t)(bb0 + bl1) * H_ + jg] = make_float2(v10, v11);
                }
            }
        }
        asm volatile("barrier.cluster.arrive.aligned;" ::: "memory");
        asm volatile("barrier.cluster.wait.aligned;" ::: "memory");
    }

    // ================= fused FC epilogue (2 batches per CTA) =================
    __syncthreads();
    if (out_off >= 0) {
        const int myb0 = bb0 + (jcb << 1);
        float* hs = (float*)smem;    // reuse stage area: [2][512] fp32
        for (int u = tid; u < 2 * H_; u += NTHR) {
            int b = u >> 9, k = u & 511;
            hs[u] = __ldcg(&g_hfin[(size_t)(myb0 + b) * H_ + k]);
        }
        __syncthreads();
        int w = tid >> 5, ln = tid & 31;
        if (w < 8) {
            int b  = w >> 2;
            int ob = (w & 3) << 2;
            #pragma unroll
            for (int oo = 0; oo < 4; oo++) {
                int o = ob + oo;
                float s = 0.f;
                #pragma unroll 4
                for (int k = ln; k < H_; k += 32)
                    s += hs[b * H_ + k] * Wfc[(size_t)o * H_ + k];
                #pragma unroll
                for (int d = 16; d > 0; d >>= 1)
                    s += __shfl_down_sync(0xFFFFFFFFu, s, d);
                if (ln == 0)
                    out[out_off + (size_t)(myb0 + b) * O_ + o] = s + bfc[o];
            }
        }
    }
}

extern "C" void kernel_launch(void* const* d_in, const int* in_sizes, int n_in,
                              void* d_out, int out_size) {
    const float* x    = (const float*)d_in[0];
    const float* h0   = (const float*)d_in[1];
    const float* W_ih = (const float*)d_in[2];
    const float* W_hh = (const float*)d_in[3];
    const float* b_ih = (const float*)d_in[4];
    const float* b_hh = (const float*)d_in[5];
    const float* W_fc = (const float*)d_in[6];
    const float* b_fc = (const float*)d_in[7];
    float* out = (float*)d_out;

    cudaFuncSetAttribute(rnn_kernel,
                         cudaFuncAttributeMaxDynamicSharedMemorySize, SMEM_BYTES);

    xp_kernel<<<dim3(T_, 64), 256>>>(x, W_ih, b_ih, b_hh);
    h0_kernel<<<512, 256>>>(h0);
    rnn_kernel<<<dim3(CLX, GRID_Y), NTHR, SMEM_BYTES>>>(W_hh, W_fc, b_fc, out, out_size);
}

// round 11
// speedup vs baseline: 2.9800x; 1.5060x over previous
#include <cuda_runtime.h>
#include <cuda_fp16.h>
#include <cstdint>

#define B_ 256
#define T_ 512
#define H_ 512
#define O_ 16
#define NTHR 512
#define CLX 8
#define GRID_Y 16

#define KTOT 576          // 0..511 = h/W_hh, 512..575 = x/W_ih
#define KQ   144          // k per quarter (per-warp k-slice)
#define KS   9            // k16 steps per quarter

#define PITCHB 1168       // stage row pitch bytes (584 f16; 1168%128=16 -> ldsm conflict-free)
#define SM_HHI 0          // 16 rows x 1168 B
#define SM_HLO 18688
#define SM_R   37376      // split-K partials: 3*4*32*2 float4 = 12288 B
#define SMEM_BYTES 49664

#define SC 2048.0f
#define INV_SC 4.8828125e-4f
#define X_ELEMS (256u * 512u * 64u)

// f16 exchange (hi / scaled-lo), ping-pong; x split; final h
__device__ __half g_hHi[2][B_][H_];
__device__ __half g_hLo[2][B_][H_];
__device__ __half g_xHi[(size_t)B_ * T_ * 64];
__device__ __half g_xLo[(size_t)B_ * T_ * 64];
__device__ float  g_hfin[B_ * H_];

// ---------------- helpers ----------------
__device__ __forceinline__ uint32_t smem_u32(const void* p) {
    uint32_t a;
    asm("{ .reg .u64 t; cvta.to.shared.u64 t, %1; cvt.u32.u64 %0, t; }" : "=r"(a) : "l"(p));
    return a;
}
__device__ __forceinline__ void mma16816(float* d, const uint32_t* a, const uint32_t* b) {
    asm volatile(
        "mma.sync.aligned.m16n8k16.row.col.f32.f16.f16.f32 "
        "{%0,%1,%2,%3}, {%4,%5,%6,%7}, {%8,%9}, {%0,%1,%2,%3};"
        : "+f"(d[0]), "+f"(d[1]), "+f"(d[2]), "+f"(d[3])
        : "r"(a[0]), "r"(a[1]), "r"(a[2]), "r"(a[3]), "r"(b[0]), "r"(b[1]));
}
__device__ __forceinline__ void ldsm4(uint32_t* a, uint32_t addr) {
    asm volatile("ldmatrix.sync.aligned.m8n8.x4.shared.b16 {%0,%1,%2,%3}, [%4];"
                 : "=r"(a[0]), "=r"(a[1]), "=r"(a[2]), "=r"(a[3]) : "r"(addr));
}
__device__ __forceinline__ uint32_t pack_hilo(float v0, float v1, uint32_t& lo) {
    __half h0 = __float2half_rn(v0), h1 = __float2half_rn(v1);
    __half l0 = __float2half_rn((v0 - __half2float(h0)) * SC);
    __half l1 = __float2half_rn((v1 - __half2float(h1)) * SC);
    __half2 lp = __halves2half2(l0, l1);
    lo = *reinterpret_cast<uint32_t*>(&lp);
    __half2 hp = __halves2half2(h0, h1);
    return *reinterpret_cast<uint32_t*>(&hp);
}

// ---------------- pre-kernel: split x and h0 into f16 hi / scaled-lo ----------------
__global__ void __launch_bounds__(256) presplit_kernel(const float* __restrict__ x,
                                                       const float* __restrict__ h0) {
    size_t e = ((size_t)blockIdx.x * 256 + threadIdx.x) * 4;
    if (e < X_ELEMS) {
        float4 v = *(const float4*)(x + e);
        uint32_t lo0, lo1;
        uint32_t hi0 = pack_hilo(v.x, v.y, lo0);
        uint32_t hi1 = pack_hilo(v.z, v.w, lo1);
        *(uint2*)&g_xHi[e] = make_uint2(hi0, hi1);
        *(uint2*)&g_xLo[e] = make_uint2(lo0, lo1);
    } else {
        size_t e2 = e - X_ELEMS;
        if (e2 < (size_t)B_ * H_) {
            float4 v = *(const float4*)(h0 + e2);
            uint32_t lo0, lo1;
            uint32_t hi0 = pack_hilo(v.x, v.y, lo0);
            uint32_t hi1 = pack_hilo(v.z, v.w, lo1);
            *(uint2*)&g_hHi[0][0][e2] = make_uint2(hi0, hi1);
            *(uint2*)&g_hLo[0][0][e2] = make_uint2(lo0, lo1);
        }
    }
}

// ---------------- main persistent RNN kernel ----------------
__global__ void __launch_bounds__(NTHR, 1) __cluster_dims__(CLX, 1, 1)
rnn_kernel(const float* __restrict__ Whh, const float* __restrict__ Wih,
           const float* __restrict__ bih, const float* __restrict__ bhh,
           const float* __restrict__ Wfc, const float* __restrict__ bfc,
           float* __restrict__ out, int out_size) {
    extern __shared__ char smem[];
    const uint32_t hh_b = smem_u32(smem + SM_HHI);
    const uint32_t hl_b = smem_u32(smem + SM_HLO);
    float4* rbuf = (float4*)(smem + SM_R);

    const int tid = threadIdx.x, lane = tid & 31, warp = tid >> 5;
    const int ng = warp & 3;          // n-group: j0 = ng*16 (2 mma n8 frags)
    const int kq = warp >> 2;         // k-quarter: k in [kq*144, kq*144+144)
    const int jcb = blockIdx.x, bg = blockIdx.y;
    const int hc0 = jcb * 64, bb0 = bg * 16;

    // ---- One-time: B fragments (W hi only) into registers ----
    uint32_t bfrag[2][KS][2];
    {
        #pragma unroll
        for (int nf = 0; nf < 2; nf++) {
            const int jB = hc0 + ng * 16 + nf * 8 + (lane >> 2);
            #pragma unroll
            for (int ks = 0; ks < KS; ks++) {
                #pragma unroll
                for (int r = 0; r < 2; r++) {
                    int kb = kq * KQ + ks * 16 + (lane & 3) * 2 + r * 8;
                    float2 w = (kb < 512)
                        ? *(const float2*)&Whh[(size_t)jB * 512 + kb]
                        : *(const float2*)&Wih[(size_t)jB * 64 + (kb - 512)];
                    __half2 h2 = __floats2half2_rn(w.x, w.y);
                    bfrag[nf][ks][r] = *reinterpret_cast<uint32_t*>(&h2);
                }
            }
        }
    }

    // Epilogue constants (kq==0 warps)
    const int bl0 = lane >> 2, bl1 = bl0 + 8;
    int jj[2];
    float2 bias[2];
    #pragma unroll
    for (int nf = 0; nf < 2; nf++) {
        jj[nf] = hc0 + ng * 16 + nf * 8 + (lane & 3) * 2;
        bias[nf] = make_float2(bih[jj[nf]] + bhh[jj[nf]], bih[jj[nf] + 1] + bhh[jj[nf] + 1]);
    }

    int out_off = -1, h_off = -1;
    if (out_size >= B_ * O_ + B_ * H_)      { out_off = 0; h_off = B_ * O_; }
    else if (out_size == B_ * O_)           { out_off = 0; }
    else if (out_size == B_ * H_)           { h_off = 0; }
    else                                    { out_off = 0; }

    const int srow = warp;            // stage row (batch) this warp fills
    const uint32_t la_hi = hh_b + (lane & 15) * PITCHB + ((lane >> 4) * 8 + kq * KQ) * 2;
    const uint32_t la_lo = hl_b + (lane & 15) * PITCHB + ((lane >> 4) * 8 + kq * KQ) * 2;

    // prefetch x(0)
    uint32_t xh = *(const uint32_t*)&g_xHi[((size_t)(bb0 + srow) * T_ + 0) * 64 + lane * 2];
    uint32_t xl = *(const uint32_t*)&g_xLo[((size_t)(bb0 + srow) * T_ + 0) * 64 + lane * 2];

    for (int t = 0; t < T_; t++) {
        const int ping = t & 1, pong = ping ^ 1;

        // ---- stage h (front-batched L2 loads) + x (prefetched) ----
        uint4 qa, qb, qc, qd;
        {
            const uint4* sh = (const uint4*)&g_hHi[ping][bb0 + srow][0];
            const uint4* sl = (const uint4*)&g_hLo[ping][bb0 + srow][0];
            qa = __ldcg(sh + lane * 2); qb = __ldcg(sh + lane * 2 + 1);
            qc = __ldcg(sl + lane * 2); qd = __ldcg(sl + lane * 2 + 1);
        }
        {
            char* dh = smem + SM_HHI + srow * PITCHB;
            char* dl = smem + SM_HLO + srow * PITCHB;
            *(uint4*)(dh + lane * 32) = qa; *(uint4*)(dh + lane * 32 + 16) = qb;
            *(uint4*)(dl + lane * 32) = qc; *(uint4*)(dl + lane * 32 + 16) = qd;
            *(uint32_t*)(dh + 1024 + lane * 4) = xh;
            *(uint32_t*)(dl + 1024 + lane * 4) = xl;
        }
        __syncthreads();

        // ---- 2-pass mma over this warp's k-quarter ----
        float Dm[2][4] = {{0, 0, 0, 0}, {0, 0, 0, 0}};
        float Db[2][4] = {{0, 0, 0, 0}, {0, 0, 0, 0}};
        #pragma unroll
        for (int ks = 0; ks < KS; ks++) {
            uint32_t ah[4], al[4];
            ldsm4(ah, la_hi + ks * 32);
            ldsm4(al, la_lo + ks * 32);
            mma16816(Dm[0], ah, bfrag[0][ks]);
            mma16816(Dm[1], ah, bfrag[1][ks]);
            mma16816(Db[0], al, bfrag[0][ks]);
            mma16816(Db[1], al, bfrag[1][ks]);
        }
        float pr[2][4];
        #pragma unroll
        for (int nf = 0; nf < 2; nf++)
            #pragma unroll
            for (int p = 0; p < 4; p++)
                pr[nf][p] = Dm[nf][p] + Db[nf][p] * INV_SC;

        if (kq > 0) {
            #pragma unroll
            for (int nf = 0; nf < 2; nf++)
                rbuf[(((kq - 1) * 4 + ng) * 32 + lane) * 2 + nf] =
                    make_float4(pr[nf][0], pr[nf][1], pr[nf][2], pr[nf][3]);
        }
        __syncthreads();

        // ---- epilogue (kq==0): merge quarters, +bias, relu, split, exchange ----
        if (kq == 0) {
            #pragma unroll
            for (int nf = 0; nf < 2; nf++) {
                float4 s = make_float4(pr[nf][0], pr[nf][1], pr[nf][2], pr[nf][3]);
                #pragma unroll
                for (int q = 0; q < 3; q++) {
                    float4 p = rbuf[((q * 4 + ng) * 32 + lane) * 2 + nf];
                    s.x += p.x; s.y += p.y; s.z += p.z; s.w += p.w;
                }
                float v0 = fmaxf(s.x + bias[nf].x, 0.f);
                float v1 = fmaxf(s.y + bias[nf].y, 0.f);
                float v2 = fmaxf(s.z + bias[nf].x, 0.f);
                float v3 = fmaxf(s.w + bias[nf].y, 0.f);
                uint32_t lo0, lo1;
                uint32_t hi0 = pack_hilo(v0, v1, lo0);
                uint32_t hi1 = pack_hilo(v2, v3, lo1);
                *(uint32_t*)&g_hHi[pong][bb0 + bl0][jj[nf]] = hi0;
                *(uint32_t*)&g_hLo[pong][bb0 + bl0][jj[nf]] = lo0;
                *(uint32_t*)&g_hHi[pong][bb0 + bl1][jj[nf]] = hi1;
                *(uint32_t*)&g_hLo[pong][bb0 + bl1][jj[nf]] = lo1;
                if (t == T_ - 1) {
                    *(float2*)&g_hfin[(size_t)(bb0 + bl0) * H_ + jj[nf]] = make_float2(v0, v1);
                    *(float2*)&g_hfin[(size_t)(bb0 + bl1) * H_ + jj[nf]] = make_float2(v2, v3);
                    if (h_off >= 0) {
                        *(float2*)&out[h_off + (size_t)(bb0 + bl0) * H_ + jj[nf]] = make_float2(v0, v1);
                        *(float2*)&out[h_off + (size_t)(bb0 + bl1) * H_ + jj[nf]] = make_float2(v2, v3);
                    }
                }
            }
        }
        asm volatile("barrier.cluster.arrive.aligned;" ::: "memory");
        if (t + 1 < T_) {
            xh = *(const uint32_t*)&g_xHi[((size_t)(bb0 + srow) * T_ + t + 1) * 64 + lane * 2];
            xl = *(const uint32_t*)&g_xLo[((size_t)(bb0 + srow) * T_ + t + 1) * 64 + lane * 2];
        }
        asm volatile("barrier.cluster.wait.aligned;" ::: "memory");
    }

    // ================= fused FC epilogue (2 batches per CTA) =================
    __syncthreads();
    if (out_off >= 0) {
        const int myb0 = bb0 + (jcb << 1);
        float* hs = (float*)smem;    // reuse: [2][512] fp32
        for (int u = tid; u < 2 * H_; u += NTHR) {
            int b = u >> 9, k = u & 511;
            hs[u] = __ldcg(&g_hfin[(size_t)(myb0 + b) * H_ + k]);
        }
        __syncthreads();
        int w = tid >> 5, ln = tid & 31;
        if (w < 8) {
            int b  = w >> 2;
            int ob = (w & 3) << 2;
            #pragma unroll
            for (int oo = 0; oo < 4; oo++) {
                int o = ob + oo;
                float s = 0.f;
                #pragma unroll 4
                for (int k = ln; k < H_; k += 32)
                    s += hs[b * H_ + k] * Wfc[(size_t)o * H_ + k];
                #pragma unroll
                for (int d = 16; d > 0; d >>= 1)
                    s += __shfl_down_sync(0xFFFFFFFFu, s, d);
                if (ln == 0)
                    out[out_off + (size_t)(myb0 + b) * O_ + o] = s + bfc[o];
            }
        }
    }
}

extern "C" void kernel_launch(void* const* d_in, const int* in_sizes, int n_in,
                              void* d_out, int out_size) {
    const float* x    = (const float*)d_in[0];
    const float* h0   = (const float*)d_in[1];
    const float* W_ih = (const float*)d_in[2];
    const float* W_hh = (const float*)d_in[3];
    const float* b_ih = (const float*)d_in[4];
    const float* b_hh = (const float*)d_in[5];
    const float* W_fc = (const float*)d_in[6];
    const float* b_fc = (const float*)d_in[7];
    float* out = (float*)d_out;

    cudaFuncSetAttribute(rnn_kernel,
                         cudaFuncAttributeMaxDynamicSharedMemorySize, SMEM_BYTES);

    // x elems 8388608 -> 8192 blocks; h0 131072 -> +128 blocks
    presplit_kernel<<<8320, 256>>>(x, h0);
    rnn_kernel<<<dim3(CLX, GRID_Y), NTHR, SMEM_BYTES>>>(W_hh, W_ih, b_ih, b_hh,
                                                        W_fc, b_fc, out, out_size);
}

// round 12
// speedup vs baseline: 4.1549x; 1.3943x over previous
#include <cuda_runtime.h>
#include <cuda_fp16.h>
#include <cstdint>

#define B_ 256
#define T_ 512
#define H_ 512
#define O_ 16
#define NTHR 256
#define CLX 8
#define GRID_Y 32          // 32 batch groups of 8

#define KTOT 576           // 0..511 = h/W_hh, 512..575 = x/W_ih
#define KH   288           // k per half (per-warp k-slice)
#define KS   18            // k16 steps per half

#define PITCHB 1168        // row pitch bytes (584 f16): stride 292 words -> conflict-free
#define SM_W   0           // W f16 hi: 64 rows x 1168 B = 74752
#define SM_HI  74752       // h-hi stage: 8 rows x 1168 B
#define SM_LO  84096       // h-lo stage
#define SM_DUM 93440       // dummy row for junk ldsm lanes
#define SM_R   94608       // split-K partials: 4*32*2 float4 = 4096
#define SMEM_BYTES 98704

#define SC 2048.0f
#define INV_SC 4.8828125e-4f
#define X_ELEMS (256u * 512u * 64u)

// f16 exchange (hi / scaled-lo), ping-pong; x split; final h
__device__ __half g_hHi[2][B_][H_];
__device__ __half g_hLo[2][B_][H_];
__device__ __half g_xHi[(size_t)B_ * T_ * 64];
__device__ __half g_xLo[(size_t)B_ * T_ * 64];
__device__ float  g_hfin[B_ * H_];

// ---------------- helpers ----------------
__device__ __forceinline__ uint32_t smem_u32(const void* p) {
    uint32_t a;
    asm("{ .reg .u64 t; cvta.to.shared.u64 t, %1; cvt.u32.u64 %0, t; }" : "=r"(a) : "l"(p));
    return a;
}
__device__ __forceinline__ void mma16816(float* d, const uint32_t* a, const uint32_t* b) {
    asm volatile(
        "mma.sync.aligned.m16n8k16.row.col.f32.f16.f16.f32 "
        "{%0,%1,%2,%3}, {%4,%5,%6,%7}, {%8,%9}, {%0,%1,%2,%3};"
        : "+f"(d[0]), "+f"(d[1]), "+f"(d[2]), "+f"(d[3])
        : "r"(a[0]), "r"(a[1]), "r"(a[2]), "r"(a[3]), "r"(b[0]), "r"(b[1]));
}
__device__ __forceinline__ void ldsm4(uint32_t* a, uint32_t addr) {
    asm volatile("ldmatrix.sync.aligned.m8n8.x4.shared.b16 {%0,%1,%2,%3}, [%4];"
                 : "=r"(a[0]), "=r"(a[1]), "=r"(a[2]), "=r"(a[3]) : "r"(addr));
}
__device__ __forceinline__ void ldsm2(uint32_t* a, uint32_t addr) {
    asm volatile("ldmatrix.sync.aligned.m8n8.x2.shared.b16 {%0,%1}, [%2];"
                 : "=r"(a[0]), "=r"(a[1]) : "r"(addr));
}
__device__ __forceinline__ uint32_t pack_hilo(float v0, float v1, uint32_t& lo) {
    __half h0 = __float2half_rn(v0), h1 = __float2half_rn(v1);
    __half l0 = __float2half_rn((v0 - __half2float(h0)) * SC);
    __half l1 = __float2half_rn((v1 - __half2float(h1)) * SC);
    __half2 lp = __halves2half2(l0, l1);
    lo = *reinterpret_cast<uint32_t*>(&lp);
    __half2 hp = __halves2half2(h0, h1);
    return *reinterpret_cast<uint32_t*>(&hp);
}

// ---------------- pre-kernel: split x and h0 into f16 hi / scaled-lo ----------------
__global__ void __launch_bounds__(256) presplit_kernel(const float* __restrict__ x,
                                                       const float* __restrict__ h0) {
    size_t e = ((size_t)blockIdx.x * 256 + threadIdx.x) * 4;
    if (e < X_ELEMS) {
        float4 v = *(const float4*)(x + e);
        uint32_t lo0, lo1;
        uint32_t hi0 = pack_hilo(v.x, v.y, lo0);
        uint32_t hi1 = pack_hilo(v.z, v.w, lo1);
        *(uint2*)&g_xHi[e] = make_uint2(hi0, hi1);
        *(uint2*)&g_xLo[e] = make_uint2(lo0, lo1);
    } else {
        size_t e2 = e - X_ELEMS;
        if (e2 < (size_t)B_ * H_) {
            float4 v = *(const float4*)(h0 + e2);
            uint32_t lo0, lo1;
            uint32_t hi0 = pack_hilo(v.x, v.y, lo0);
            uint32_t hi1 = pack_hilo(v.z, v.w, lo1);
            *(uint2*)&g_hHi[0][0][e2] = make_uint2(hi0, hi1);
            *(uint2*)&g_hLo[0][0][e2] = make_uint2(lo0, lo1);
        }
    }
}

// ---------------- main persistent RNN kernel (2 CTAs/SM) ----------------
__global__ void __launch_bounds__(NTHR, 2) __cluster_dims__(CLX, 1, 1)
rnn_kernel(const float* __restrict__ Whh, const float* __restrict__ Wih,
           const float* __restrict__ bih, const float* __restrict__ bhh,
           const float* __restrict__ Wfc, const float* __restrict__ bfc,
           float* __restrict__ out, int out_size) {
    extern __shared__ char smem[];
    const uint32_t wb   = smem_u32(smem + SM_W);
    const uint32_t hh_b = smem_u32(smem + SM_HI);
    const uint32_t hl_b = smem_u32(smem + SM_LO);
    const uint32_t dm_b = smem_u32(smem + SM_DUM);
    float4* rbuf = (float4*)(smem + SM_R);

    const int tid = threadIdx.x, lane = tid & 31, warp = tid >> 5;
    const int ng = warp & 3;          // n-group: j0 = ng*16 (2 mma n8 frags)
    const int kh = warp >> 2;         // k-half: [kh*288, kh*288+288)
    const int jcb = blockIdx.x, bg = blockIdx.y;
    const int hc0 = jcb * 64, bb0 = bg * 8;

    // ---- One-time: W chunk (hi only, f16) into SMEM rows [j][k] ----
    for (int u = tid; u < 64 * KTOT; u += NTHR) {
        int j = u / KTOT, k = u - j * KTOT;
        float w = (k < 512) ? Whh[(size_t)(hc0 + j) * 512 + k]
                            : Wih[(size_t)(hc0 + j) * 64 + (k - 512)];
        *(__half*)(smem + SM_W + j * PITCHB + k * 2) = __float2half_rn(w);
    }
    if (tid < 292) *(uint32_t*)(smem + SM_DUM + tid * 4) = 0;   // dummy row

    // Epilogue constants
    const int bl0 = lane >> 2;                       // real batch row 0..7
    int jj[2];
    float2 bias[2];
    #pragma unroll
    for (int nf = 0; nf < 2; nf++) {
        jj[nf] = hc0 + ng * 16 + nf * 8 + (lane & 3) * 2;
        bias[nf] = make_float2(bih[jj[nf]] + bhh[jj[nf]], bih[jj[nf] + 1] + bhh[jj[nf] + 1]);
    }

    int out_off = -1, h_off = -1;
    if (out_size >= B_ * O_ + B_ * H_)      { out_off = 0; h_off = B_ * O_; }
    else if (out_size == B_ * O_)           { out_off = 0; }
    else if (out_size == B_ * H_)           { h_off = 0; }
    else                                    { out_off = 0; }

    // ldsm A addresses: rows = lane&7 (real) or dummy; col half by lane>>4
    const int lrow = lane & 7;
    const int junk = (lane >> 3) & 1;
    const uint32_t la_hi = junk ? dm_b : (hh_b + lrow * PITCHB + (lane >> 4) * 16 + kh * (KH * 2));
    const uint32_t la_lo = junk ? dm_b : (hl_b + lrow * PITCHB + (lane >> 4) * 16 + kh * (KH * 2));
    // ldsm B addresses (x2, lanes 0-15): rows = j, matrix sel by bit3
    const int l16 = lane & 15;
    uint32_t lb[2];
    #pragma unroll
    for (int nf = 0; nf < 2; nf++)
        lb[nf] = wb + (ng * 16 + nf * 8 + (l16 & 7)) * PITCHB + ((l16 >> 3) * 8 + kh * KH) * 2;

    const int srow = warp;            // stage row (batch) this warp fills (8 warps, 8 rows)

    // prefetch x(0)
    uint32_t xh = *(const uint32_t*)&g_xHi[((size_t)(bb0 + srow) * T_ + 0) * 64 + lane * 2];
    uint32_t xl = *(const uint32_t*)&g_xLo[((size_t)(bb0 + srow) * T_ + 0) * 64 + lane * 2];
    __syncthreads();

    for (int t = 0; t < T_; t++) {
        const int ping = t & 1, pong = ping ^ 1;

        // ---- stage h (front-batched L2 loads) + x (prefetched) ----
        uint4 qa, qb, qc, qd;
        {
            const uint4* sh = (const uint4*)&g_hHi[ping][bb0 + srow][0];
            const uint4* sl = (const uint4*)&g_hLo[ping][bb0 + srow][0];
            qa = __ldcg(sh + lane * 2); qb = __ldcg(sh + lane * 2 + 1);
            qc = __ldcg(sl + lane * 2); qd = __ldcg(sl + lane * 2 + 1);
        }
        {
            char* dh = smem + SM_HI + srow * PITCHB;
            char* dl = smem + SM_LO + srow * PITCHB;
            *(uint4*)(dh + lane * 32) = qa; *(uint4*)(dh + lane * 32 + 16) = qb;
            *(uint4*)(dl + lane * 32) = qc; *(uint4*)(dl + lane * 32 + 16) = qd;
            *(uint32_t*)(dh + 1024 + lane * 4) = xh;
            *(uint32_t*)(dl + 1024 + lane * 4) = xl;
        }
        __syncthreads();

        // ---- 2-pass mma over this warp's k-half (B frags from SMEM) ----
        float Dm[2][4] = {{0, 0, 0, 0}, {0, 0, 0, 0}};
        float Db[2][4] = {{0, 0, 0, 0}, {0, 0, 0, 0}};
        #pragma unroll
        for (int ks = 0; ks < KS; ks++) {
            uint32_t ah[4], al[4], b0[2], b1[2];
            ldsm4(ah, la_hi + (junk ? 0 : ks * 32));
            ldsm4(al, la_lo + (junk ? 0 : ks * 32));
            ldsm2(b0, lb[0] + ks * 32);
            ldsm2(b1, lb[1] + ks * 32);
            mma16816(Dm[0], ah, b0);
            mma16816(Dm[1], ah, b1);
            mma16816(Db[0], al, b0);
            mma16816(Db[1], al, b1);
        }
        float pr[2][4];
        #pragma unroll
        for (int nf = 0; nf < 2; nf++)
            #pragma unroll
            for (int p = 0; p < 4; p++)
                pr[nf][p] = Dm[nf][p] + Db[nf][p] * INV_SC;

        if (kh == 1) {
            #pragma unroll
            for (int nf = 0; nf < 2; nf++)
                rbuf[(ng * 32 + lane) * 2 + nf] =
                    make_float4(pr[nf][0], pr[nf][1], pr[nf][2], pr[nf][3]);
        }
        __syncthreads();

        // ---- epilogue (kh==0): merge halves, +bias, relu, split, exchange ----
        if (kh == 0) {
            #pragma unroll
            for (int nf = 0; nf < 2; nf++) {
                float4 p = rbuf[(ng * 32 + lane) * 2 + nf];
                float v0 = fmaxf(pr[nf][0] + p.x + bias[nf].x, 0.f);
                float v1 = fmaxf(pr[nf][1] + p.y + bias[nf].y, 0.f);
                uint32_t lo0;
                uint32_t hi0 = pack_hilo(v0, v1, lo0);
                *(uint32_t*)&g_hHi[pong][bb0 + bl0][jj[nf]] = hi0;
                *(uint32_t*)&g_hLo[pong][bb0 + bl0][jj[nf]] = lo0;
                if (t == T_ - 1) {
                    *(float2*)&g_hfin[(size_t)(bb0 + bl0) * H_ + jj[nf]] = make_float2(v0, v1);
                    if (h_off >= 0)
                        *(float2*)&out[h_off + (size_t)(bb0 + bl0) * H_ + jj[nf]] =
                            make_float2(v0, v1);
                }
            }
        }
        asm volatile("barrier.cluster.arrive.aligned;" ::: "memory");
        if (t + 1 < T_) {
            xh = *(const uint32_t*)&g_xHi[((size_t)(bb0 + srow) * T_ + t + 1) * 64 + lane * 2];
            xl = *(const uint32_t*)&g_xLo[((size_t)(bb0 + srow) * T_ + t + 1) * 64 + lane * 2];
        }
        asm volatile("barrier.cluster.wait.aligned;" ::: "memory");
    }

    // ================= fused FC epilogue (1 batch per CTA) =================
    __syncthreads();
    if (out_off >= 0) {
        const int myb = bb0 + jcb;
        float* hs = (float*)smem;    // reuse: [512] fp32
        for (int u = tid; u < H_; u += NTHR)
            hs[u] = __ldcg(&g_hfin[(size_t)myb * H_ + u]);
        __syncthreads();
        int w = tid >> 5, ln = tid & 31;
        if (w < 4) {
            #pragma unroll
            for (int oo = 0; oo < 4; oo++) {
                int o = w * 4 + oo;
                float s = 0.f;
                #pragma unroll 4
                for (int k = ln; k < H_; k += 32)
                    s += hs[k] * Wfc[(size_t)o * H_ + k];
                #pragma unroll
                for (int d = 16; d > 0; d >>= 1)
                    s += __shfl_down_sync(0xFFFFFFFFu, s, d);
                if (ln == 0)
                    out[out_off + (size_t)myb * O_ + o] = s + bfc[o];
            }
        }
    }
}

extern "C" void kernel_launch(void* const* d_in, const int* in_sizes, int n_in,
                              void* d_out, int out_size) {
    const float* x    = (const float*)d_in[0];
    const float* h0   = (const float*)d_in[1];
    const float* W_ih = (const float*)d_in[2];
    const float* W_hh = (const float*)d_in[3];
    const float* b_ih = (const float*)d_in[4];
    const float* b_hh = (const float*)d_in[5];
    const float* W_fc = (const float*)d_in[6];
    const float* b_fc = (const float*)d_in[7];
    float* out = (float*)d_out;

    cudaFuncSetAttribute(rnn_kernel,
                         cudaFuncAttributeMaxDynamicSharedMemorySize, SMEM_BYTES);

    presplit_kernel<<<8320, 256>>>(x, h0);
    rnn_kernel<<<dim3(CLX, GRID_Y), NTHR, SMEM_BYTES>>>(W_hh, W_ih, b_ih, b_hh,
                                                        W_fc, b_fc, out, out_size);
}

// round 13
// speedup vs baseline: 5.1964x; 1.2507x over previous
#include <cuda_runtime.h>
#include <cuda_fp16.h>
#include <cstdint>

#define B_ 256
#define T_ 512
#define H_ 512
#define O_ 16
#define NTHR 256
#define CLX 8
#define GRID_Y 32          // 32 batch groups of 8

#define KTOT 576           // 0..511 = h/W_hh, 512..575 = x/W_ih
#define KH   288           // k per half (per-warp k-slice)
#define KS   18            // k16 steps per half

#define PITCHB 1168        // row pitch bytes (584 f16): stride 292 words -> conflict-free
#define SM_W   0           // W f16 hi: 64 rows x 1168 B = 74752
#define SM_ST  74752       // A stage: 16 rows x 1168 B (rows 0-7 = h_hi, 8-15 = h_lo)
#define SM_R   93440       // split-K partials: 4*32*2 float2 = 2048 B
#define SMEM_BYTES 95488

#define SC 2048.0f
#define INV_SC 4.8828125e-4f
#define X_ELEMS (256u * 512u * 64u)

// f16 exchange (hi / scaled-lo), ping-pong; x split; final h
__device__ __half g_hHi[2][B_][H_];
__device__ __half g_hLo[2][B_][H_];
__device__ __half g_xHi[(size_t)B_ * T_ * 64];
__device__ __half g_xLo[(size_t)B_ * T_ * 64];
__device__ float  g_hfin[B_ * H_];

// ---------------- helpers ----------------
__device__ __forceinline__ uint32_t smem_u32(const void* p) {
    uint32_t a;
    asm("{ .reg .u64 t; cvta.to.shared.u64 t, %1; cvt.u32.u64 %0, t; }" : "=r"(a) : "l"(p));
    return a;
}
__device__ __forceinline__ void mma16816(float* d, const uint32_t* a, const uint32_t* b) {
    asm volatile(
        "mma.sync.aligned.m16n8k16.row.col.f32.f16.f16.f32 "
        "{%0,%1,%2,%3}, {%4,%5,%6,%7}, {%8,%9}, {%0,%1,%2,%3};"
        : "+f"(d[0]), "+f"(d[1]), "+f"(d[2]), "+f"(d[3])
        : "r"(a[0]), "r"(a[1]), "r"(a[2]), "r"(a[3]), "r"(b[0]), "r"(b[1]));
}
__device__ __forceinline__ void ldsm4(uint32_t* a, uint32_t addr) {
    asm volatile("ldmatrix.sync.aligned.m8n8.x4.shared.b16 {%0,%1,%2,%3}, [%4];"
                 : "=r"(a[0]), "=r"(a[1]), "=r"(a[2]), "=r"(a[3]) : "r"(addr));
}
__device__ __forceinline__ uint32_t pack_hilo(float v0, float v1, uint32_t& lo) {
    __half h0 = __float2half_rn(v0), h1 = __float2half_rn(v1);
    __half l0 = __float2half_rn((v0 - __half2float(h0)) * SC);
    __half l1 = __float2half_rn((v1 - __half2float(h1)) * SC);
    __half2 lp = __halves2half2(l0, l1);
    lo = *reinterpret_cast<uint32_t*>(&lp);
    __half2 hp = __halves2half2(h0, h1);
    return *reinterpret_cast<uint32_t*>(&hp);
}

// ---------------- pre-kernel: split x and h0 into f16 hi / scaled-lo ----------------
__global__ void __launch_bounds__(256) presplit_kernel(const float* __restrict__ x,
                                                       const float* __restrict__ h0) {
    size_t e = ((size_t)blockIdx.x * 256 + threadIdx.x) * 4;
    if (e < X_ELEMS) {
        float4 v = *(const float4*)(x + e);
        uint32_t lo0, lo1;
        uint32_t hi0 = pack_hilo(v.x, v.y, lo0);
        uint32_t hi1 = pack_hilo(v.z, v.w, lo1);
        *(uint2*)&g_xHi[e] = make_uint2(hi0, hi1);
        *(uint2*)&g_xLo[e] = make_uint2(lo0, lo1);
    } else {
        size_t e2 = e - X_ELEMS;
        if (e2 < (size_t)B_ * H_) {
            float4 v = *(const float4*)(h0 + e2);
            uint32_t lo0, lo1;
            uint32_t hi0 = pack_hilo(v.x, v.y, lo0);
            uint32_t hi1 = pack_hilo(v.z, v.w, lo1);
            *(uint2*)&g_hHi[0][0][e2] = make_uint2(hi0, hi1);
            *(uint2*)&g_hLo[0][0][e2] = make_uint2(lo0, lo1);
        }
    }
}

// ---------------- main persistent RNN kernel (2 CTAs/SM, hi/lo packed in M) ----------------
__global__ void __launch_bounds__(NTHR, 2) __cluster_dims__(CLX, 1, 1)
rnn_kernel(const float* __restrict__ Whh, const float* __restrict__ Wih,
           const float* __restrict__ bih, const float* __restrict__ bhh,
           const float* __restrict__ Wfc, const float* __restrict__ bfc,
           float* __restrict__ out, int out_size) {
    extern __shared__ char smem[];
    const uint32_t wb   = smem_u32(smem + SM_W);
    const uint32_t st_b = smem_u32(smem + SM_ST);
    float2* rbuf = (float2*)(smem + SM_R);

    const int tid = threadIdx.x, lane = tid & 31, warp = tid >> 5;
    const int ng = warp & 3;          // n-group: j0 = ng*16 (2 mma n8 frags)
    const int kh = warp >> 2;         // k-half: [kh*288, kh*288+288)
    const int jcb = blockIdx.x, bg = blockIdx.y;
    const int hc0 = jcb * 64, bb0 = bg * 8;

    // ---- One-time: W chunk (hi only, f16) into SMEM rows [j][k] ----
    for (int u = tid; u < 64 * KTOT; u += NTHR) {
        int j = u / KTOT, k = u - j * KTOT;
        float w = (k < 512) ? Whh[(size_t)(hc0 + j) * 512 + k]
                            : Wih[(size_t)(hc0 + j) * 64 + (k - 512)];
        *(__half*)(smem + SM_W + j * PITCHB + k * 2) = __float2half_rn(w);
    }

    // Epilogue constants
    const int bl0 = lane >> 2;                       // batch row 0..7
    int jj[2];
    float2 bias[2];
    #pragma unroll
    for (int nf = 0; nf < 2; nf++) {
        jj[nf] = hc0 + ng * 16 + nf * 8 + (lane & 3) * 2;
        bias[nf] = make_float2(bih[jj[nf]] + bhh[jj[nf]], bih[jj[nf] + 1] + bhh[jj[nf] + 1]);
    }

    int out_off = -1, h_off = -1;
    if (out_size >= B_ * O_ + B_ * H_)      { out_off = 0; h_off = B_ * O_; }
    else if (out_size == B_ * O_)           { out_off = 0; }
    else if (out_size == B_ * H_)           { h_off = 0; }
    else                                    { out_off = 0; }

    // ldsm A: rows 0-15 (0-7 hi, 8-15 lo), x4 matrices (m0:r0-7/k0, m1:r8-15/k0, m2:r0-7/k8, m3:r8-15/k8)
    const uint32_t la = st_b + (lane & 15) * PITCHB + ((lane >> 4) * 8 + kh * KH) * 2;
    // ldsm B x4: m0 = nf0/k0, m1 = nf0/k8, m2 = nf1/k0, m3 = nf1/k8
    const uint32_t lbq = wb + (ng * 16 + (lane >> 4) * 8 + (lane & 7)) * PITCHB +
                         (((lane >> 3) & 1) * 8 + kh * KH) * 2;

    const int srow = warp;            // batch row this warp stages (8 warps, 8 rows)

    // prefetch x(0)
    uint32_t xh = *(const uint32_t*)&g_xHi[((size_t)(bb0 + srow) * T_ + 0) * 64 + lane * 2];
    uint32_t xl = *(const uint32_t*)&g_xLo[((size_t)(bb0 + srow) * T_ + 0) * 64 + lane * 2];
    __syncthreads();

    for (int t = 0; t < T_; t++) {
        const int ping = t & 1, pong = ping ^ 1;

        // ---- stage h: hi -> row srow, lo -> row srow+8 ; x at k 512.. ----
        uint4 qa, qb, qc, qd;
        {
            const uint4* sh = (const uint4*)&g_hHi[ping][bb0 + srow][0];
            const uint4* sl = (const uint4*)&g_hLo[ping][bb0 + srow][0];
            qa = __ldcg(sh + lane * 2); qb = __ldcg(sh + lane * 2 + 1);
            qc = __ldcg(sl + lane * 2); qd = __ldcg(sl + lane * 2 + 1);
        }
        {
            char* dh = smem + SM_ST + srow * PITCHB;
            char* dl = smem + SM_ST + (srow + 8) * PITCHB;
            *(uint4*)(dh + lane * 32) = qa; *(uint4*)(dh + lane * 32 + 16) = qb;
            *(uint4*)(dl + lane * 32) = qc; *(uint4*)(dl + lane * 32 + 16) = qd;
            *(uint32_t*)(dh + 1024 + lane * 4) = xh;
            *(uint32_t*)(dl + 1024 + lane * 4) = xl;
        }
        __syncthreads();

        // ---- mma over this warp's k-half: 2 LDSM + 2 MMA per k16 ----
        float Dm[2][4] = {{0, 0, 0, 0}, {0, 0, 0, 0}};
        #pragma unroll
        for (int ks = 0; ks < KS; ks++) {
            uint32_t a[4], bq[4];
            ldsm4(a, la + ks * 32);
            ldsm4(bq, lbq + ks * 32);
            mma16816(Dm[0], a, bq);        // nf0: b frag = {bq[0], bq[1]}
            mma16816(Dm[1], a, bq + 2);    // nf1: b frag = {bq[2], bq[3]}
        }
        // merge hi (rows 0-7 -> d0,d1) with lo (rows 8-15 -> d2,d3)
        float2 pr[2];
        #pragma unroll
        for (int nf = 0; nf < 2; nf++)
            pr[nf] = make_float2(Dm[nf][0] + Dm[nf][2] * INV_SC,
                                 Dm[nf][1] + Dm[nf][3] * INV_SC);

        if (kh == 1) {
            #pragma unroll
            for (int nf = 0; nf < 2; nf++)
                rbuf[(ng * 32 + lane) * 2 + nf] = pr[nf];
        }
        __syncthreads();

        // ---- epilogue (kh==0): merge halves, +bias, relu, split, exchange ----
        if (kh == 0) {
            #pragma unroll
            for (int nf = 0; nf < 2; nf++) {
                float2 p = rbuf[(ng * 32 + lane) * 2 + nf];
                float v0 = fmaxf(pr[nf].x + p.x + bias[nf].x, 0.f);
                float v1 = fmaxf(pr[nf].y + p.y + bias[nf].y, 0.f);
                uint32_t lo0;
                uint32_t hi0 = pack_hilo(v0, v1, lo0);
                *(uint32_t*)&g_hHi[pong][bb0 + bl0][jj[nf]] = hi0;
                *(uint32_t*)&g_hLo[pong][bb0 + bl0][jj[nf]] = lo0;
                if (t == T_ - 1) {
                    *(float2*)&g_hfin[(size_t)(bb0 + bl0) * H_ + jj[nf]] = make_float2(v0, v1);
                    if (h_off >= 0)
                        *(float2*)&out[h_off + (size_t)(bb0 + bl0) * H_ + jj[nf]] =
                            make_float2(v0, v1);
                }
            }
        }
        asm volatile("barrier.cluster.arrive.aligned;" ::: "memory");
        if (t + 1 < T_) {
            xh = *(const uint32_t*)&g_xHi[((size_t)(bb0 + srow) * T_ + t + 1) * 64 + lane * 2];
            xl = *(const uint32_t*)&g_xLo[((size_t)(bb0 + srow) * T_ + t + 1) * 64 + lane * 2];
        }
        asm volatile("barrier.cluster.wait.aligned;" ::: "memory");
    }

    // ================= fused FC epilogue (1 batch per CTA) =================
    __syncthreads();
    if (out_off >= 0) {
        const int myb = bb0 + jcb;
        float* hs = (float*)smem;    // reuse: [512] fp32
        for (int u = tid; u < H_; u += NTHR)
            hs[u] = __ldcg(&g_hfin[(size_t)myb * H_ + u]);
        __syncthreads();
        int w = tid >> 5, ln = tid & 31;
        if (w < 4) {
            #pragma unroll
            for (int oo = 0; oo < 4; oo++) {
                int o = w * 4 + oo;
                float s = 0.f;
                #pragma unroll 4
                for (int k = ln; k < H_; k += 32)
                    s += hs[k] * Wfc[(size_t)o * H_ + k];
                #pragma unroll
                for (int d = 16; d > 0; d >>= 1)
                    s += __shfl_down_sync(0xFFFFFFFFu, s, d);
                if (ln == 0)
                    out[out_off + (size_t)myb * O_ + o] = s + bfc[o];
            }
        }
    }
}

extern "C" void kernel_launch(void* const* d_in, const int* in_sizes, int n_in,
                              void* d_out, int out_size) {
    const float* x    = (const float*)d_in[0];
    const float* h0   = (const float*)d_in[1];
    const float* W_ih = (const float*)d_in[2];
    const float* W_hh = (const float*)d_in[3];
    const float* b_ih = (const float*)d_in[4];
    const float* b_hh = (const float*)d_in[5];
    const float* W_fc = (const float*)d_in[6];
    const float* b_fc = (const float*)d_in[7];
    float* out = (float*)d_out;

    cudaFuncSetAttribute(rnn_kernel,
                         cudaFuncAttributeMaxDynamicSharedMemorySize, SMEM_BYTES);

    presplit_kernel<<<8320, 256>>>(x, h0);
    rnn_kernel<<<dim3(CLX, GRID_Y), NTHR, SMEM_BYTES>>>(W_hh, W_ih, b_ih, b_hh,
                                                        W_fc, b_fc, out, out_size);
}